// round 15
// baseline (speedup 1.0000x reference)
#include <cuda_runtime.h>
#include <cuda_bf16.h>
#include <cstdint>

#define BB 4
#define LL 4096
#define DD 1024
#define MM 512
#define CH 16
#define CHLEN 32

typedef unsigned long long u64;
typedef unsigned int u32;

// ---------------- scratch (static device arrays; no runtime alloc) ----------
__device__ float g_smoothed[BB * MM * DD];      // 8 MB
__device__ int   g_pbidx[BB * LL];              // 64 KB
__device__ float g_chainA[BB * CH];
__device__ float g_chainB[BB * CH * DD];        // 256 KB
// Tiled + swizzled tf32 operands:
//   g_atf: [rowTile(128)][chunk(32)][row(128)][32 words]  (64 MB)
//   g_wtf: [colTile(8)  ][chunk(32)][row(128)][32 words]  (4 MB)
__device__ u32   g_atf[BB * LL * DD];
__device__ u32   g_wtf[DD * DD];

__device__ __forceinline__ u32 smem_u32(const void* p) {
    u32 a;
    asm("{ .reg .u64 t; cvta.to.shared.u64 t, %1; cvt.u32.u64 %0, t; }" : "=r"(a) : "l"(p));
    return a;
}
__device__ __forceinline__ u32 f2tf32(float v) {
    u32 r;
    asm("cvt.rna.tf32.f32 %0, %1;" : "=r"(r) : "f"(v));
    return r;
}

#define MBAR_INIT(a, c) \
    asm volatile("mbarrier.init.shared.b64 [%0], %1;" :: "r"(a), "r"((u32)(c)) : "memory")
#define MBAR_EXPECT_TX(a, b) \
    asm volatile("mbarrier.arrive.expect_tx.shared.b64 _, [%0], %1;" :: "r"(a), "r"((u32)(b)) : "memory")
#define MBAR_ARRIVE(a) \
    asm volatile("mbarrier.arrive.shared.b64 _, [%0];" :: "r"(a) : "memory")
#define BULK_G2S(dst, src, sz, mb) \
    asm volatile("cp.async.bulk.shared::cluster.global.mbarrier::complete_tx::bytes " \
                 "[%0], [%1], %2, [%3];" \
                 :: "r"(dst), "l"(src), "r"((u32)(sz)), "r"(mb) : "memory")
#define MBAR_WAIT(addr, phase) do {                                              \
    asm volatile(                                                                \
        "{\n\t.reg .pred P;\n\t"                                                 \
        "WL%=:\n\t"                                                              \
        "mbarrier.try_wait.parity.acquire.cta.shared::cta.b64 P, [%0], %1, 0x989680;\n\t" \
        "@P bra.uni WD%=;\n\t"                                                   \
        "bra.uni WL%=;\n\t"                                                      \
        "WD%=:\n\t}"                                                             \
        :: "r"(addr), "r"((u32)(phase)) : "memory");                             \
} while (0)

// ---------------------------------------------------------------------------
// preconv_all: fp32 -> tf32 bits for BOTH enc and W, writing the TILED,
// PRE-SWIZZLED layout consumed by bulk-DMA in the GEMM.
// ---------------------------------------------------------------------------
#define N8_ENC (BB * LL * DD / 8)   // 2097152
#define N8_W   (DD * DD / 8)        // 131072

__global__ void preconv_all(const float* __restrict__ enc,
                            const float* __restrict__ Wm,
                            u32* __restrict__ atf, u32* __restrict__ wtf)
{
    int i = blockIdx.x * blockDim.x + threadIdx.x;
    const float* x;
    u32* y;
    int j;
    if (i < N8_ENC)              { x = enc; y = atf; j = i; }
    else if (i < N8_ENC + N8_W)  { x = Wm;  y = wtf; j = i - N8_ENC; }
    else return;

    const int r = j >> 7;           // global row (m or e)
    const int q = j & 127;          // 8-k group index within row
    float4 v0 = ((const float4*)x)[j * 2];
    float4 v1 = ((const float4*)x)[j * 2 + 1];
    uint4 o0, o1;
    o0.x = f2tf32(v0.x); o0.y = f2tf32(v1.x); o0.z = f2tf32(v0.y); o0.w = f2tf32(v1.y);
    o1.x = f2tf32(v0.z); o1.y = f2tf32(v1.z); o1.z = f2tf32(v0.w); o1.w = f2tf32(v1.w);

    const int tile = r >> 7, rowIn = r & 127;
    const int chunk = q >> 2, jj = q & 3;
    const u32 wbase = (u32)(((tile * 32 + chunk) * 128 + rowIn)) << 5;  // *32 words
    const u32 col0 = (u32)((jj * 8 + 8 * (r & 3)) & 31);                // in {0,8,16,24}
    uint4* y4 = (uint4*)y;
    y4[(wbase + col0) >> 2]     = o0;
    y4[(wbase + col0 + 4) >> 2] = o1;
}

// ---------------------------------------------------------------------------
// EMA phase 1: per-chunk local scan, 1024-thread blocks.
// ---------------------------------------------------------------------------
__global__ void ema1(const float* __restrict__ ct, const float* __restrict__ bp,
                     const int* __restrict__ bidx)
{
    const int c = blockIdx.x, b = blockIdx.y, d = threadIdx.x;
    __shared__ float p[CHLEN];
    const bool is64 = (bidx[1] == 0 && bidx[3] == 0);
    if (d < CHLEN) {
        int w = b * MM + c * CHLEN + d;
        if (is64) w <<= 1;
        p[d] = fmaxf(bp[b * LL + bidx[w]], 0.1f);
    }
    __syncthreads();

    const float* cb = ct + ((size_t)(b * MM + c * CHLEN)) * DD + d;
    float* sb = g_smoothed + ((size_t)(b * MM + c * CHLEN)) * DD + d;
    float h = 0.0f;
    int i0 = 0;
    if (c == 0) { h = cb[0]; sb[0] = h; i0 = 1; }
    for (int i = i0; i < CHLEN; i++) {
        float pm = p[i];
        float a = fmaxf(1.0f - pm, 1e-7f);
        h = a * h + pm * cb[(size_t)i * DD];
        sb[(size_t)i * DD] = h;
    }
    g_chainB[(b * CH + c) * DD + d] = h;
    if (d == 0) {
        float A = 1.0f;
        for (int i = i0; i < CHLEN; i++) A *= fmaxf(1.0f - p[i], 1e-7f);
        g_chainA[b * CH + c] = A;
    }
}

// ---------------------------------------------------------------------------
// EMA phase 2: fold chunk summaries -> h_in, add prefix*h_in to local scans.
// ---------------------------------------------------------------------------
__global__ void ema2(const float* __restrict__ bp, const int* __restrict__ bidx)
{
    const int c = blockIdx.x + 1, b = blockIdx.y, d = threadIdx.x;
    __shared__ float p[CHLEN];
    __shared__ float Aj[CH];
    const bool is64 = (bidx[1] == 0 && bidx[3] == 0);
    if (d < CHLEN) {
        int w = b * MM + c * CHLEN + d;
        if (is64) w <<= 1;
        p[d] = fmaxf(bp[b * LL + bidx[w]], 0.1f);
    }
    if (d >= 32 && d < 32 + CH) Aj[d - 32] = g_chainA[b * CH + (d - 32)];
    __syncthreads();

    float hin = 0.0f;
    for (int j = 0; j < c; j++)
        hin = Aj[j] * hin + g_chainB[(b * CH + j) * DD + d];

    float* sb = g_smoothed + ((size_t)(b * MM + c * CHLEN)) * DD + d;
    float pref = 1.0f;
    for (int i = 0; i < CHLEN; i++) {
        pref *= fmaxf(1.0f - p[i], 1e-7f);
        sb[(size_t)i * DD] += pref * hin;
    }
}

// ---------------------------------------------------------------------------
// plug_back_idx = clip(cumsum(bp >= 0.5) - 1, 0)
// ---------------------------------------------------------------------------
__global__ void pbidx_kernel(const float* __restrict__ bp)
{
    const int b = blockIdx.x, t = threadIdx.x;
    __shared__ int s[1024];
    const float* row = bp + b * LL;
    int loc[4];
    int cnt = 0;
#pragma unroll
    for (int i = 0; i < 4; i++) {
        cnt += (row[t * 4 + i] >= 0.5f) ? 1 : 0;
        loc[i] = cnt;
    }
    s[t] = cnt;
    __syncthreads();
    for (int off = 1; off < 1024; off <<= 1) {
        int add = (t >= off) ? s[t - off] : 0;
        __syncthreads();
        s[t] += add;
        __syncthreads();
    }
    int excl = s[t] - cnt;
#pragma unroll
    for (int i = 0; i < 4; i++) {
        int v = excl + loc[i] - 1;
        g_pbidx[b * LL + t * 4 + i] = v < 0 ? 0 : v;
    }
}

// ---------------------------------------------------------------------------
// TF32 GEMM: 64x64 warp tiles (frag bytes/MMA -33%), 4 warps (2m x 2n),
// 128 threads, 3 CTAs/SM. Bulk-DMA loads, 2-stage full/consumed mbarrier
// rings, no __syncthreads in the chunk loop.
// ---------------------------------------------------------------------------
#define KC 32
#define NCHUNK 32
#define NSTAGE 2
#define TILE_B 16384                   // 128 rows x 32 words x 4B
#define STAGE_B (2 * TILE_B)           // 32768 (A + B)
#define MBAR_OFF (NSTAGE * STAGE_B)    // 65536
#define SMEM_TOT (NSTAGE * STAGE_B + 64)

__global__ void __launch_bounds__(128, 3)
gemm_tf32(float* __restrict__ out)
{
    extern __shared__ char smem[];
    const u32 sbase = smem_u32(smem);
    const int tid = threadIdx.x;
    const int wid = tid >> 5, lane = tid & 31;
    const int rowTile = blockIdx.y;        // 128-row tile
    const int colTile = blockIdx.x;        // 128-col tile
    const int rowBase = rowTile * 128;
    const int colBase = colTile * 128;
    const int wm = (wid >> 1) * 64;        // 2 m-warps
    const int wn = (wid & 1) * 64;         // 2 n-warps
    const int g = lane >> 2, tq = lane & 3;
    const int rot = 8 * (g & 3);           // swizzle rotation for this lane

    const u32 fullb = sbase + MBAR_OFF;    // 2 full barriers (8B apart)
    const u32 consb = fullb + 16;          // 2 consumed barriers

    if (tid == 0) {
        MBAR_INIT(fullb, 1);      MBAR_INIT(fullb + 8, 1);
        MBAR_INIT(consb, 4);      MBAR_INIT(consb + 8, 4);
    }
    __syncthreads();

    const u32* srcA = g_atf + (size_t)rowTile * 32 * 4096;  // per-chunk 16KB blocks
    const u32* srcB = g_wtf + (size_t)colTile * 32 * 4096;

    auto issue = [&](int t, int s) {
        u32 mb = fullb + (u32)s * 8;
        u32 st = sbase + (u32)s * STAGE_B;
        MBAR_EXPECT_TX(mb, 2 * TILE_B);
        BULK_G2S(st,          srcA + (size_t)t * 4096, TILE_B, mb);
        BULK_G2S(st + TILE_B, srcB + (size_t)t * 4096, TILE_B, mb);
    };

    float acc[4][8][4];
#pragma unroll
    for (int i = 0; i < 4; i++)
#pragma unroll
        for (int j = 0; j < 8; j++)
#pragma unroll
            for (int k = 0; k < 4; k++) acc[i][j][k] = 0.0f;

    if (tid == 0) { issue(0, 0); issue(1, 1); }

    int stage = 0, ph = 0;
    for (int t = 0; t < NCHUNK; t++) {
        const u32 fmb = fullb + (u32)stage * 8;
        const u32 cmb = consb + (u32)stage * 8;
        MBAR_WAIT(fmb, ph);    // per-thread acquire: chunk t data visible

        const u32* saw = (const u32*)(smem + (size_t)stage * STAGE_B);
        const u32* sbw = saw + TILE_B / 4;
        const u32* pa = saw + (wm + g) * 32;
        const u32* pb = sbw + (wn + g) * 32;

#pragma unroll
        for (int ks = 0; ks < 4; ks++) {
            const int off = (ks * 8 + tq * 2 + rot) & 31;  // swizzled pair (k,k+4)
            u32 a[4][4];
#pragma unroll
            for (int mi = 0; mi < 4; mi++) {
                uint2 lo = *(const uint2*)(pa + (mi * 16)     * 32 + off);
                uint2 hi = *(const uint2*)(pa + (mi * 16 + 8) * 32 + off);
                a[mi][0] = lo.x; a[mi][1] = hi.x; a[mi][2] = lo.y; a[mi][3] = hi.y;
            }
            // Stream B fragments: one uint2 per n8, 4 MMAs each.
#pragma unroll
            for (int n8 = 0; n8 < 8; n8++) {
                uint2 bb = *(const uint2*)(pb + (n8 * 8) * 32 + off);
#pragma unroll
                for (int mi = 0; mi < 4; mi++) {
                    asm volatile(
                        "mma.sync.aligned.m16n8k8.row.col.f32.tf32.tf32.f32 "
                        "{%0,%1,%2,%3}, {%4,%5,%6,%7}, {%8,%9}, {%0,%1,%2,%3};"
                        : "+f"(acc[mi][n8][0]), "+f"(acc[mi][n8][1]),
                          "+f"(acc[mi][n8][2]), "+f"(acc[mi][n8][3])
                        : "r"(a[mi][0]), "r"(a[mi][1]), "r"(a[mi][2]), "r"(a[mi][3]),
                          "r"(bb.x), "r"(bb.y));
                }
            }
        }

        // This warp is done reading stage `stage` for chunk t.
        if (lane == 0) MBAR_ARRIVE(cmb);

        // Refill: chunk t+2 goes into this same stage once ALL warps are done.
        if (t + 2 < NCHUNK && tid == 0) {
            MBAR_WAIT(cmb, ph);
            issue(t + 2, stage);
        }

        if (++stage == NSTAGE) { stage = 0; ph ^= 1; }
    }

    // Epilogue: acc d0,d1 -> row g, cols 2tq,2tq+1 ; d2,d3 -> row g+8
#pragma unroll
    for (int mi = 0; mi < 4; mi++) {
#pragma unroll
        for (int half = 0; half < 2; half++) {
            const int row = rowBase + wm + mi * 16 + g + half * 8;
            const int b = row >> 12;
            const int idx = g_pbidx[row];
            const float* sp = g_smoothed + ((size_t)(b * MM + idx)) * DD;
            float* op = out + (size_t)row * DD;
#pragma unroll
            for (int n8 = 0; n8 < 8; n8++) {
                const int col = colBase + wn + n8 * 8 + tq * 2;
                float2 pv = *(const float2*)(sp + col);
                float2 ov;
                ov.x = acc[mi][n8][half * 2 + 0] + pv.x;
                ov.y = acc[mi][n8][half * 2 + 1] + pv.y;
                *(float2*)(op + col) = ov;
            }
        }
    }
}

// ---------------------------------------------------------------------------
// Launch: 3-way graph fork — preconv (main), EMA chain (s2), pbidx (s3);
// join all before the GEMM.
// ---------------------------------------------------------------------------
extern "C" void kernel_launch(void* const* d_in, const int* in_sizes, int n_in,
                              void* d_out, int out_size)
{
    const float* ct = nullptr;
    const float* enc = nullptr;
    const float* bp = nullptr;
    const int* bidx = nullptr;
    const float* Wm = nullptr;

    for (int i = 0; i < n_in; i++) {
        switch (in_sizes[i]) {
            case BB * MM * DD: ct  = (const float*)d_in[i]; break;
            case BB * LL * DD: enc = (const float*)d_in[i]; break;
            case BB * LL:      bp  = (const float*)d_in[i]; break;
            case DD * DD:      Wm  = (const float*)d_in[i]; break;
            case BB * MM:      if (!bidx) bidx = (const int*)d_in[i]; break;
            default: break;
        }
    }
    float* out = (float*)d_out;

    static u32* atf_p = nullptr;
    static u32* wtf_p = nullptr;
    static cudaStream_t s2 = nullptr, s3 = nullptr;
    static cudaEvent_t evF = nullptr, evJ2 = nullptr, evJ3 = nullptr;
    if (!atf_p) {
        cudaGetSymbolAddress((void**)&atf_p, g_atf);
        cudaGetSymbolAddress((void**)&wtf_p, g_wtf);
        cudaFuncSetAttribute(gemm_tf32, cudaFuncAttributeMaxDynamicSharedMemorySize,
                             SMEM_TOT);
        cudaStreamCreateWithFlags(&s2, cudaStreamNonBlocking);
        cudaStreamCreateWithFlags(&s3, cudaStreamNonBlocking);
        cudaEventCreateWithFlags(&evF, cudaEventDisableTiming);
        cudaEventCreateWithFlags(&evJ2, cudaEventDisableTiming);
        cudaEventCreateWithFlags(&evJ3, cudaEventDisableTiming);
    }

    // Fork
    cudaEventRecord(evF, 0);
    cudaStreamWaitEvent(s2, evF, 0);
    cudaStreamWaitEvent(s3, evF, 0);

    // Branch A (main): operand conversion into tiled/swizzled layout.
    preconv_all<<<(N8_ENC + N8_W + 255) / 256, 256>>>(enc, Wm, atf_p, wtf_p);

    // Branch B (s2): EMA smoothing chain.
    ema1<<<dim3(CH, BB), 1024, 0, s2>>>(ct, bp, bidx);
    ema2<<<dim3(CH - 1, BB), 1024, 0, s2>>>(bp, bidx);

    // Branch C (s3): plugback indices (depends only on bp).
    pbidx_kernel<<<BB, 1024, 0, s3>>>(bp);

    // Join
    cudaEventRecord(evJ2, s2);
    cudaEventRecord(evJ3, s3);
    cudaStreamWaitEvent(0, evJ2, 0);
    cudaStreamWaitEvent(0, evJ3, 0);

    dim3 grid(DD / 128, (BB * LL) / 128);   // (8, 128)
    gemm_tf32<<<grid, 128, SMEM_TOT>>>(out);
}

// round 16
// speedup vs baseline: 1.4940x; 1.4940x over previous
#include <cuda_runtime.h>
#include <cuda_bf16.h>
#include <cstdint>

#define BB 4
#define LL 4096
#define DD 1024
#define MM 512
#define CH 16
#define CHLEN 32

typedef unsigned long long u64;
typedef unsigned int u32;

// ---------------- scratch (static device arrays; no runtime alloc) ----------
__device__ float g_smoothed[BB * MM * DD];      // 8 MB
__device__ int   g_pbidx[BB * LL];              // 64 KB
__device__ float g_chainA[BB * CH];
__device__ float g_chainB[BB * CH * DD];        // 256 KB
// Tiled + swizzled tf32 operands:
//   g_atf: [rowTile(128)][chunk(32)][row(128)][32 words]  (64 MB)
//   g_wtf: [colTile(8)  ][chunk(32)][row(128)][32 words]  (4 MB)
__device__ u32   g_atf[BB * LL * DD];
__device__ u32   g_wtf[DD * DD];

__device__ __forceinline__ u32 smem_u32(const void* p) {
    u32 a;
    asm("{ .reg .u64 t; cvta.to.shared.u64 t, %1; cvt.u32.u64 %0, t; }" : "=r"(a) : "l"(p));
    return a;
}
__device__ __forceinline__ u32 f2tf32(float v) {
    u32 r;
    asm("cvt.rna.tf32.f32 %0, %1;" : "=r"(r) : "f"(v));
    return r;
}

#define MBAR_INIT(a, c) \
    asm volatile("mbarrier.init.shared.b64 [%0], %1;" :: "r"(a), "r"((u32)(c)) : "memory")
#define MBAR_EXPECT_TX(a, b) \
    asm volatile("mbarrier.arrive.expect_tx.shared.b64 _, [%0], %1;" :: "r"(a), "r"((u32)(b)) : "memory")
#define MBAR_ARRIVE(a) \
    asm volatile("mbarrier.arrive.shared.b64 _, [%0];" :: "r"(a) : "memory")
#define BULK_G2S(dst, src, sz, mb) \
    asm volatile("cp.async.bulk.shared::cluster.global.mbarrier::complete_tx::bytes " \
                 "[%0], [%1], %2, [%3];" \
                 :: "r"(dst), "l"(src), "r"((u32)(sz)), "r"(mb) : "memory")
#define MBAR_WAIT(addr, phase) do {                                              \
    asm volatile(                                                                \
        "{\n\t.reg .pred P;\n\t"                                                 \
        "WL%=:\n\t"                                                              \
        "mbarrier.try_wait.parity.acquire.cta.shared::cta.b64 P, [%0], %1, 0x989680;\n\t" \
        "@P bra.uni WD%=;\n\t"                                                   \
        "bra.uni WL%=;\n\t"                                                      \
        "WD%=:\n\t}"                                                             \
        :: "r"(addr), "r"((u32)(phase)) : "memory");                             \
} while (0)

// ---------------------------------------------------------------------------
// preconv_all: fp32 -> tf32 bits for BOTH enc and W, writing the TILED,
// PRE-SWIZZLED layout consumed by bulk-DMA in the GEMM. Per 8-k group the
// pair permutation [k0,k4,k1,k5,k2,k6,k3,k7] is preserved.
// ---------------------------------------------------------------------------
#define N8_ENC (BB * LL * DD / 8)   // 2097152
#define N8_W   (DD * DD / 8)        // 131072

__global__ void preconv_all(const float* __restrict__ enc,
                            const float* __restrict__ Wm,
                            u32* __restrict__ atf, u32* __restrict__ wtf)
{
    int i = blockIdx.x * blockDim.x + threadIdx.x;
    const float* x;
    u32* y;
    int j;
    if (i < N8_ENC)              { x = enc; y = atf; j = i; }
    else if (i < N8_ENC + N8_W)  { x = Wm;  y = wtf; j = i - N8_ENC; }
    else return;

    const int r = j >> 7;           // global row (m or e)
    const int q = j & 127;          // 8-k group index within row
    float4 v0 = ((const float4*)x)[j * 2];
    float4 v1 = ((const float4*)x)[j * 2 + 1];
    uint4 o0, o1;
    o0.x = f2tf32(v0.x); o0.y = f2tf32(v1.x); o0.z = f2tf32(v0.y); o0.w = f2tf32(v1.y);
    o1.x = f2tf32(v0.z); o1.y = f2tf32(v1.z); o1.z = f2tf32(v0.w); o1.w = f2tf32(v1.w);

    const int tile = r >> 7, rowIn = r & 127;
    const int chunk = q >> 2, jj = q & 3;
    const u32 wbase = (u32)(((tile * 32 + chunk) * 128 + rowIn)) << 5;  // *32 words
    const u32 col0 = (u32)((jj * 8 + 8 * (r & 3)) & 31);                // in {0,8,16,24}
    uint4* y4 = (uint4*)y;
    y4[(wbase + col0) >> 2]     = o0;
    y4[(wbase + col0 + 4) >> 2] = o1;
}

// ---------------------------------------------------------------------------
// EMA phase 1: per-chunk local scan, 1024-thread blocks.
// ---------------------------------------------------------------------------
__global__ void ema1(const float* __restrict__ ct, const float* __restrict__ bp,
                     const int* __restrict__ bidx)
{
    const int c = blockIdx.x, b = blockIdx.y, d = threadIdx.x;
    __shared__ float p[CHLEN];
    const bool is64 = (bidx[1] == 0 && bidx[3] == 0);
    if (d < CHLEN) {
        int w = b * MM + c * CHLEN + d;
        if (is64) w <<= 1;
        p[d] = fmaxf(bp[b * LL + bidx[w]], 0.1f);
    }
    __syncthreads();

    const float* cb = ct + ((size_t)(b * MM + c * CHLEN)) * DD + d;
    float* sb = g_smoothed + ((size_t)(b * MM + c * CHLEN)) * DD + d;
    float h = 0.0f;
    int i0 = 0;
    if (c == 0) { h = cb[0]; sb[0] = h; i0 = 1; }
    for (int i = i0; i < CHLEN; i++) {
        float pm = p[i];
        float a = fmaxf(1.0f - pm, 1e-7f);
        h = a * h + pm * cb[(size_t)i * DD];
        sb[(size_t)i * DD] = h;
    }
    g_chainB[(b * CH + c) * DD + d] = h;
    if (d == 0) {
        float A = 1.0f;
        for (int i = i0; i < CHLEN; i++) A *= fmaxf(1.0f - p[i], 1e-7f);
        g_chainA[b * CH + c] = A;
    }
}

// ---------------------------------------------------------------------------
// EMA phase 2: fold chunk summaries -> h_in, add prefix*h_in to local scans.
// ---------------------------------------------------------------------------
__global__ void ema2(const float* __restrict__ bp, const int* __restrict__ bidx)
{
    const int c = blockIdx.x + 1, b = blockIdx.y, d = threadIdx.x;
    __shared__ float p[CHLEN];
    __shared__ float Aj[CH];
    const bool is64 = (bidx[1] == 0 && bidx[3] == 0);
    if (d < CHLEN) {
        int w = b * MM + c * CHLEN + d;
        if (is64) w <<= 1;
        p[d] = fmaxf(bp[b * LL + bidx[w]], 0.1f);
    }
    if (d >= 32 && d < 32 + CH) Aj[d - 32] = g_chainA[b * CH + (d - 32)];
    __syncthreads();

    float hin = 0.0f;
    for (int j = 0; j < c; j++)
        hin = Aj[j] * hin + g_chainB[(b * CH + j) * DD + d];

    float* sb = g_smoothed + ((size_t)(b * MM + c * CHLEN)) * DD + d;
    float pref = 1.0f;
    for (int i = 0; i < CHLEN; i++) {
        pref *= fmaxf(1.0f - p[i], 1e-7f);
        sb[(size_t)i * DD] += pref * hin;
    }
}

// ---------------------------------------------------------------------------
// plug_back_idx = clip(cumsum(bp >= 0.5) - 1, 0)
// ---------------------------------------------------------------------------
__global__ void pbidx_kernel(const float* __restrict__ bp)
{
    const int b = blockIdx.x, t = threadIdx.x;
    __shared__ int s[1024];
    const float* row = bp + b * LL;
    int loc[4];
    int cnt = 0;
#pragma unroll
    for (int i = 0; i < 4; i++) {
        cnt += (row[t * 4 + i] >= 0.5f) ? 1 : 0;
        loc[i] = cnt;
    }
    s[t] = cnt;
    __syncthreads();
    for (int off = 1; off < 1024; off <<= 1) {
        int add = (t >= off) ? s[t - off] : 0;
        __syncthreads();
        s[t] += add;
        __syncthreads();
    }
    int excl = s[t] - cnt;
#pragma unroll
    for (int i = 0; i < 4; i++) {
        int v = excl + loc[i] - 1;
        g_pbidx[b * LL + t * 4 + i] = v < 0 ? 0 : v;
    }
}

// ---------------------------------------------------------------------------
// TF32 GEMM (R14 base): bulk-DMA loads, 3-stage full/consumed mbarrier rings,
// no __syncthreads in the chunk loop. Refill duty ROTATES across warps
// (wid == t&7) so no single warp is re-convoyed to the slowest warp each chunk.
// Block 128x128, 8 warps (2m x 4n), warp 64x32, 2 CTAs/SM.
// ---------------------------------------------------------------------------
#define KC 32
#define NCHUNK 32
#define TILE_B 16384                   // 128 rows x 32 words x 4B
#define STAGE_B (2 * TILE_B)           // 32768 (A + B)
#define MBAR_OFF (3 * STAGE_B)         // 98304
#define SMEM_TOT (3 * STAGE_B + 64)    // stages + 6 mbarriers

__global__ void __launch_bounds__(256, 2)
gemm_tf32(float* __restrict__ out)
{
    extern __shared__ char smem[];
    const u32 sbase = smem_u32(smem);
    const int tid = threadIdx.x;
    const int wid = tid >> 5, lane = tid & 31;
    const int rowTile = blockIdx.y;        // 128-row tile
    const int colTile = blockIdx.x;        // 128-col tile
    const int rowBase = rowTile * 128;
    const int colBase = colTile * 128;
    const int wm = (wid >> 2) * 64;        // 2 m-warps
    const int wn = (wid & 3) * 32;         // 4 n-warps
    const int g = lane >> 2, tq = lane & 3;
    const int rot = 8 * (g & 3);           // swizzle rotation for this lane

    const u32 fullb = sbase + MBAR_OFF;    // 3 full barriers (8B apart)
    const u32 consb = fullb + 24;          // 3 consumed barriers

    if (tid == 0) {
        MBAR_INIT(fullb, 1);      MBAR_INIT(fullb + 8, 1);  MBAR_INIT(fullb + 16, 1);
        MBAR_INIT(consb, 8);      MBAR_INIT(consb + 8, 8);  MBAR_INIT(consb + 16, 8);
    }
    __syncthreads();

    const u32* srcA = g_atf + (size_t)rowTile * 32 * 4096;  // per-chunk 16KB blocks
    const u32* srcB = g_wtf + (size_t)colTile * 32 * 4096;

    auto issue = [&](int t, int s) {
        u32 mb = fullb + (u32)s * 8;
        u32 st = sbase + (u32)s * STAGE_B;
        MBAR_EXPECT_TX(mb, 2 * TILE_B);
        BULK_G2S(st,          srcA + (size_t)t * 4096, TILE_B, mb);
        BULK_G2S(st + TILE_B, srcB + (size_t)t * 4096, TILE_B, mb);
    };

    float acc[4][4][4];
#pragma unroll
    for (int i = 0; i < 4; i++)
#pragma unroll
        for (int j = 0; j < 4; j++)
#pragma unroll
            for (int k = 0; k < 4; k++) acc[i][j][k] = 0.0f;

    if (tid == 0) { issue(0, 0); issue(1, 1); issue(2, 2); }

    int stage = 0, ph = 0;
    for (int t = 0; t < NCHUNK; t++) {
        const u32 fmb = fullb + (u32)stage * 8;
        const u32 cmb = consb + (u32)stage * 8;
        MBAR_WAIT(fmb, ph);    // per-thread acquire: chunk t data visible

        const u32* saw = (const u32*)(smem + (size_t)stage * STAGE_B);
        const u32* sbw = saw + TILE_B / 4;
        const u32* pa = saw + (wm + g) * 32;
        const u32* pb = sbw + (wn + g) * 32;

#pragma unroll
        for (int ks = 0; ks < 4; ks++) {
            const int off = (ks * 8 + tq * 2 + rot) & 31;  // swizzled pair (k,k+4)
            u32 a[4][4];
#pragma unroll
            for (int mi = 0; mi < 4; mi++) {
                uint2 lo = *(const uint2*)(pa + (mi * 16)     * 32 + off);
                uint2 hi = *(const uint2*)(pa + (mi * 16 + 8) * 32 + off);
                a[mi][0] = lo.x; a[mi][1] = hi.x; a[mi][2] = lo.y; a[mi][3] = hi.y;
            }
            u32 bf[4][2];
#pragma unroll
            for (int n8 = 0; n8 < 4; n8++) {
                uint2 bb = *(const uint2*)(pb + (n8 * 8) * 32 + off);
                bf[n8][0] = bb.x; bf[n8][1] = bb.y;
            }
#pragma unroll
            for (int mi = 0; mi < 4; mi++)
#pragma unroll
                for (int n8 = 0; n8 < 4; n8++) {
                    asm volatile(
                        "mma.sync.aligned.m16n8k8.row.col.f32.tf32.tf32.f32 "
                        "{%0,%1,%2,%3}, {%4,%5,%6,%7}, {%8,%9}, {%0,%1,%2,%3};"
                        : "+f"(acc[mi][n8][0]), "+f"(acc[mi][n8][1]),
                          "+f"(acc[mi][n8][2]), "+f"(acc[mi][n8][3])
                        : "r"(a[mi][0]), "r"(a[mi][1]), "r"(a[mi][2]), "r"(a[mi][3]),
                          "r"(bf[n8][0]), "r"(bf[n8][1]));
                }
        }

        // This warp is done reading stage `stage` for chunk t.
        if (lane == 0) MBAR_ARRIVE(cmb);

        // Refill: rotating duty warp waits for ALL warps, then issues t+3
        // into this same stage. Rotation spreads the convoy cost 1/8 per warp.
        if (t + 3 < NCHUNK && wid == (t & 7) && lane == 0) {
            MBAR_WAIT(cmb, ph);
            issue(t + 3, stage);
        }

        if (++stage == 3) { stage = 0; ph ^= 1; }
    }

    // Epilogue: acc d0,d1 -> row g, cols 2tq,2tq+1 ; d2,d3 -> row g+8
#pragma unroll
    for (int mi = 0; mi < 4; mi++) {
#pragma unroll
        for (int half = 0; half < 2; half++) {
            const int row = rowBase + wm + mi * 16 + g + half * 8;
            const int b = row >> 12;
            const int idx = g_pbidx[row];
            const float* sp = g_smoothed + ((size_t)(b * MM + idx)) * DD;
            float* op = out + (size_t)row * DD;
#pragma unroll
            for (int n8 = 0; n8 < 4; n8++) {
                const int col = colBase + wn + n8 * 8 + tq * 2;
                float2 pv = *(const float2*)(sp + col);
                float2 ov;
                ov.x = acc[mi][n8][half * 2 + 0] + pv.x;
                ov.y = acc[mi][n8][half * 2 + 1] + pv.y;
                *(float2*)(op + col) = ov;
            }
        }
    }
}

// ---------------------------------------------------------------------------
// Launch: 3-way graph fork with PRIORITY side streams — EMA chain and pbidx
// get SM placement ahead of preconv's 8192 blocks; join before the GEMM.
// ---------------------------------------------------------------------------
extern "C" void kernel_launch(void* const* d_in, const int* in_sizes, int n_in,
                              void* d_out, int out_size)
{
    const float* ct = nullptr;
    const float* enc = nullptr;
    const float* bp = nullptr;
    const int* bidx = nullptr;
    const float* Wm = nullptr;

    for (int i = 0; i < n_in; i++) {
        switch (in_sizes[i]) {
            case BB * MM * DD: ct  = (const float*)d_in[i]; break;
            case BB * LL * DD: enc = (const float*)d_in[i]; break;
            case BB * LL:      bp  = (const float*)d_in[i]; break;
            case DD * DD:      Wm  = (const float*)d_in[i]; break;
            case BB * MM:      if (!bidx) bidx = (const int*)d_in[i]; break;
            default: break;
        }
    }
    float* out = (float*)d_out;

    static u32* atf_p = nullptr;
    static u32* wtf_p = nullptr;
    static cudaStream_t s2 = nullptr, s3 = nullptr;
    static cudaEvent_t evF = nullptr, evJ2 = nullptr, evJ3 = nullptr;
    if (!atf_p) {
        cudaGetSymbolAddress((void**)&atf_p, g_atf);
        cudaGetSymbolAddress((void**)&wtf_p, g_wtf);
        cudaFuncSetAttribute(gemm_tf32, cudaFuncAttributeMaxDynamicSharedMemorySize,
                             SMEM_TOT);
        int prLo = 0, prHi = 0;
        cudaDeviceGetStreamPriorityRange(&prLo, &prHi);   // prHi = highest
        cudaStreamCreateWithPriority(&s2, cudaStreamNonBlocking, prHi);
        cudaStreamCreateWithPriority(&s3, cudaStreamNonBlocking, prHi);
        cudaEventCreateWithFlags(&evF, cudaEventDisableTiming);
        cudaEventCreateWithFlags(&evJ2, cudaEventDisableTiming);
        cudaEventCreateWithFlags(&evJ3, cudaEventDisableTiming);
    }

    // Fork
    cudaEventRecord(evF, 0);
    cudaStreamWaitEvent(s2, evF, 0);
    cudaStreamWaitEvent(s3, evF, 0);

    // Branch B (s2, high priority): EMA smoothing chain.
    ema1<<<dim3(CH, BB), 1024, 0, s2>>>(ct, bp, bidx);
    ema2<<<dim3(CH - 1, BB), 1024, 0, s2>>>(bp, bidx);

    // Branch C (s3, high priority): plugback indices (depends only on bp).
    pbidx_kernel<<<BB, 1024, 0, s3>>>(bp);

    // Branch A (main): operand conversion into tiled/swizzled layout.
    preconv_all<<<(N8_ENC + N8_W + 255) / 256, 256>>>(enc, Wm, atf_p, wtf_p);

    // Join
    cudaEventRecord(evJ2, s2);
    cudaEventRecord(evJ3, s3);
    cudaStreamWaitEvent(0, evJ2, 0);
    cudaStreamWaitEvent(0, evJ3, 0);

    dim3 grid(DD / 128, (BB * LL) / 128);   // (8, 128)
    gemm_tf32<<<grid, 256, SMEM_TOT>>>(out);
}